// round 2
// baseline (speedup 1.0000x reference)
#include <cuda_runtime.h>
#include <cuda_bf16.h>

#define THREADS 512
#define VT      128000
#define VS      32000
#define KSEL    256
#define MAXB    2048
#define SBINS   4096

// monotone float->uint key
__device__ __forceinline__ unsigned f2k(float x) {
    unsigned u = __float_as_uint(x);
    return (u & 0x80000000u) ? ~u : (u | 0x80000000u);
}
__device__ __forceinline__ float k2f(unsigned k) {
    unsigned u = (k & 0x80000000u) ? (k & 0x7fffffffu) : ~k;
    return __uint_as_float(u);
}

// Scan 4096-bin hist from the top; find bin where cumulative crosses Kneed.
__device__ void select_bin4096(const unsigned* hist, unsigned* scanbuf, unsigned Kneed,
                               int tid, int* s_bin, unsigned* s_above) {
    unsigned local[8];
    unsigned part = 0;
#pragma unroll
    for (int j = 0; j < 8; j++) {
        local[j] = hist[(SBINS - 1) - (tid * 8 + j)];
        part += local[j];
    }
    scanbuf[tid] = part;
    __syncthreads();
    for (int off = 1; off < THREADS; off <<= 1) {
        unsigned v = (tid >= off) ? scanbuf[tid - off] : 0u;
        __syncthreads();
        scanbuf[tid] += v;
        __syncthreads();
    }
    unsigned incl = scanbuf[tid];
    unsigned before = incl - part;
    if (before < Kneed && incl >= Kneed) {
        unsigned cum = before;
#pragma unroll
        for (int j = 0; j < 8; j++) {
            unsigned c = local[j];
            if (cum + c >= Kneed) {
                *s_bin = (SBINS - 1) - (tid * 8 + j);
                *s_above = cum;
                break;
            }
            cum += c;
        }
    }
    __syncthreads();
}

// Same for a 256-bin histogram.
__device__ void select_bin256(const unsigned* hist, unsigned* scanbuf, unsigned Kneed,
                              int tid, int* s_bin, unsigned* s_above) {
    unsigned cnt = 0;
    if (tid < 256) {
        cnt = hist[255 - tid];
        scanbuf[tid] = cnt;
    }
    __syncthreads();
    for (int off = 1; off < 256; off <<= 1) {
        unsigned v = (tid >= off && tid < 256) ? scanbuf[tid - off] : 0u;
        __syncthreads();
        if (tid < 256) scanbuf[tid] += v;
        __syncthreads();
    }
    if (tid < 256) {
        unsigned incl = scanbuf[tid];
        unsigned before = incl - cnt;
        if (before < Kneed && incl >= Kneed) {
            *s_bin = 255 - tid;
            *s_above = before;
        }
    }
    __syncthreads();
}

__global__ void __launch_bounds__(THREADS, 3)
vocab_project_kernel(const float* __restrict__ logits,
                     const void* __restrict__ mapping,
                     float* __restrict__ out) {
    // pool: phase1 = 4096-bin sample hist; phase2 = 256-bin hist + ping-pong tier arrays
    __shared__ unsigned pool[256 + 2 * MAXB];     // 4608 words = 18KB (>= 4096 for phase1)
    __shared__ unsigned candKey[MAXB], candIdx[MAXB];
    __shared__ unsigned scanbuf[THREADS];
    __shared__ unsigned selKey[KSEL], selIdx[KSEL];
    __shared__ float    selW[KSEL];
    __shared__ int      selSid[KSEL];
    __shared__ int      s_bin;
    __shared__ unsigned s_above;
    __shared__ int      nCand, selCount, nNext, s_is64;
    __shared__ unsigned s_maxkey;

    const int tid = threadIdx.x;
    const int row = blockIdx.x;
    const float4* __restrict__ rp = (const float4*)(logits + (size_t)row * VT);
    float* __restrict__ orow = out + (size_t)row * VS;

    // ---- init + mapping dtype detect ----
    unsigned* hist = pool;
    for (int i = tid; i < SBINS; i += THREADS) hist[i] = 0u;
    if (tid == 0) {
        const unsigned* m32 = (const unsigned*)mapping;
        int all0 = 1;
        for (int i = 1; i < 64; i += 2)
            if (m32[i] != 0u) { all0 = 0; break; }
        s_is64 = all0;
        s_maxkey = 0u;
        selCount = 0;
    }
    __syncthreads();

    // ---- sample pass: every 16th float4 (8000 elems) -> 4096-bin hist ----
    for (int i = tid; i < VT / 64; i += THREADS) {
        float4 v = rp[i << 4];
        atomicAdd(&hist[f2k(v.x) >> 20], 1u);
        atomicAdd(&hist[f2k(v.y) >> 20], 1u);
        atomicAdd(&hist[f2k(v.z) >> 20], 1u);
        atomicAdd(&hist[f2k(v.w) >> 20], 1u);
    }
    __syncthreads();

    // threshold bin: sample rank 64 (~true rank 1000-1400, safely inside [KSEL, MAXB])
    select_bin4096(hist, scanbuf, 64u, tid, &s_bin, &s_above);
    int thr_bin = s_bin;

    // ---- full pass: collect (key, idx) >= threshold, warp-aggregated append ----
    for (int attempt = 0; attempt < 6; attempt++) {
        if (tid == 0) nCand = 0;
        __syncthreads();
        const unsigned thrKey = (unsigned)thr_bin << 20;
        for (int i = tid; i < VT / 4; i += THREADS) {
            float4 v = rp[i];
            float a[4] = {v.x, v.y, v.z, v.w};
#pragma unroll
            for (int j = 0; j < 4; j++) {
                unsigned key = f2k(a[j]);
                bool pred = key >= thrKey;
                unsigned mask = __ballot_sync(0xffffffffu, pred);
                if (pred) {
                    int lane = tid & 31;
                    int rank = __popc(mask & ((1u << lane) - 1u));
                    int leader = __ffs(mask) - 1;
                    unsigned base;
                    if (lane == leader) base = (unsigned)atomicAdd(&nCand, __popc(mask));
                    base = __shfl_sync(mask, base, leader);
                    unsigned p = base + rank;
                    if (p < MAXB) { candKey[p] = key; candIdx[p] = (unsigned)(i * 4 + j); }
                }
            }
        }
        __syncthreads();
        int nc = nCand;
        if (nc >= KSEL && nc <= MAXB) break;
        // adjust threshold (uniform across threads); practically never taken
        if (nc < KSEL) thr_bin = (thr_bin >= 64) ? thr_bin - 64 : 0;
        else           thr_bin = thr_bin + 1;
        __syncthreads();
    }

    // ---- zero own output row (overlaps with selection compute below) ----
    {
        float4 z = make_float4(0.f, 0.f, 0.f, 0.f);
        float4* op = (float4*)orow;
        for (int i = tid; i < VS / 4; i += THREADS) op[i] = z;
    }

    // ---- exact top-KSEL among candidates: byte-radix select (msb->lsb) ----
    unsigned* h256   = pool;
    unsigned* tmpKey = pool + 256;
    unsigned* tmpIdx = pool + 256 + MAXB;
    unsigned *curK = candKey, *curI = candIdx, *othK = tmpKey, *othI = tmpIdx;
    int curN = nCand < MAXB ? nCand : MAXB;
    int need = KSEL;
    __syncthreads();

    for (int level = 3; level >= 0; level--) {
        if (curN == need) {
            for (int p = tid; p < curN; p += THREADS) {
                int q = atomicAdd(&selCount, 1);
                selKey[q] = curK[p]; selIdx[q] = curI[p];
            }
            need = 0;
            __syncthreads();
            break;
        }
        if (tid < 256) h256[tid] = 0u;
        __syncthreads();
        const int sh = level * 8;
        for (int p = tid; p < curN; p += THREADS)
            atomicAdd(&h256[(curK[p] >> sh) & 0xFFu], 1u);
        __syncthreads();
        select_bin256(h256, scanbuf, (unsigned)need, tid, &s_bin, &s_above);
        const int c = s_bin;
        const int G = (int)s_above;
        if (tid == 0) nNext = 0;
        __syncthreads();
        for (int p = tid; p < curN; p += THREADS) {
            unsigned key = curK[p];
            int byte = (int)((key >> sh) & 0xFFu);
            if (byte > c) {
                int q = atomicAdd(&selCount, 1);
                selKey[q] = key; selIdx[q] = curI[p];
            } else if (byte == c) {
                int q = atomicAdd(&nNext, 1);
                othK[q] = key; othI[q] = curI[p];
            }
        }
        __syncthreads();
        need -= G;
        curN = nNext;
        unsigned* t;
        t = curK; curK = othK; othK = t;
        t = curI; curI = othI; othI = t;
        __syncthreads();
    }

    // remaining curN entries have IDENTICAL keys; take `need` smallest indices
    if (need > 0) {
        for (int p = tid; p < curN; p += THREADS) {
            unsigned my = curI[p];
            int rank = 0;
            for (int j = 0; j < curN; j++) rank += (curI[j] < my);
            if (rank < need) {
                int q = atomicAdd(&selCount, 1);
                selKey[q] = curK[p]; selIdx[q] = my;
            }
        }
        __syncthreads();
    }

    // ---- canonicalize: bitonic sort KSEL winners by index ascending ----
    for (int k = 2; k <= KSEL; k <<= 1) {
        for (int j = k >> 1; j > 0; j >>= 1) {
            if (tid < KSEL) {
                int ixj = tid ^ j;
                if (ixj > tid) {
                    bool up = ((tid & k) == 0);
                    unsigned a = selIdx[tid], b = selIdx[ixj];
                    if ((a > b) == up) {
                        selIdx[tid] = b; selIdx[ixj] = a;
                        unsigned t = selKey[tid]; selKey[tid] = selKey[ixj]; selKey[ixj] = t;
                    }
                }
            }
            __syncthreads();
        }
    }

    // ---- max logit over selection ----
    if (tid < KSEL) atomicMax(&s_maxkey, selKey[tid]);
    __syncthreads();
    const float vmax = k2f(s_maxkey);

    // ---- weights + deterministic fixed-order denominator ----
    float* red = (float*)scanbuf;
    if (tid < KSEL) {
        float w = exp2f((k2f(selKey[tid]) - vmax) * 0.36067376022224085f); // 1/(4 ln2)
        selW[tid] = w;
        red[tid] = w;
    }
    __syncthreads();
    for (int s = KSEL / 2; s > 0; s >>= 1) {
        if (tid < s) red[tid] += red[tid + s];
        __syncthreads();
    }
    const float inv = 1.0f / red[0];

    // ---- gather student ids ----
    if (tid < KSEL) {
        unsigned idx = selIdx[tid];
        int sid;
        if (s_is64) sid = (int)((const long long*)mapping)[idx];
        else        sid = ((const int*)mapping)[idx];
        selSid[tid] = sid;
    }
    __syncthreads();

    // ---- dedup'd deterministic scatter (list is idx-sorted => fixed sum order) ----
    if (tid < KSEL) {
        int sid = selSid[tid];
        bool first = true;
        for (int j = 0; j < tid; j++)
            if (selSid[j] == sid) { first = false; break; }
        if (first) {
            float s = 0.f;
            for (int j = tid; j < KSEL; j++)
                if (selSid[j] == sid) s += selW[j];
            orow[sid] = s * inv;
        }
    }
}

extern "C" void kernel_launch(void* const* d_in, const int* in_sizes, int n_in,
                              void* d_out, int out_size) {
    const float* logits  = (const float*)d_in[0];
    const void*  mapping = d_in[1];
    float* out = (float*)d_out;
    int rows = in_sizes[0] / VT;   // B*T = 2048
    vocab_project_kernel<<<rows, THREADS>>>(logits, mapping, out);
}

// round 3
// speedup vs baseline: 1.0342x; 1.0342x over previous
#include <cuda_runtime.h>
#include <cuda_bf16.h>

#define THREADS 512
#define VT      128000
#define VS      32000
#define KSEL    256
#define MAXB    2048
#define SBINS   4096

// monotone float->uint key
__device__ __forceinline__ unsigned f2k(float x) {
    unsigned u = __float_as_uint(x);
    return (u & 0x80000000u) ? ~u : (u | 0x80000000u);
}
__device__ __forceinline__ float k2f(unsigned k) {
    unsigned u = (k & 0x80000000u) ? (k & 0x7fffffffu) : ~k;
    return __uint_as_float(u);
}

// Scan 4096-bin hist from the top; find bin where cumulative crosses Kneed.
__device__ void select_bin4096(const unsigned* hist, unsigned* scanbuf, unsigned Kneed,
                               int tid, int* s_bin, unsigned* s_above) {
    unsigned local[8];
    unsigned part = 0;
#pragma unroll
    for (int j = 0; j < 8; j++) {
        local[j] = hist[(SBINS - 1) - (tid * 8 + j)];
        part += local[j];
    }
    scanbuf[tid] = part;
    __syncthreads();
    for (int off = 1; off < THREADS; off <<= 1) {
        unsigned v = (tid >= off) ? scanbuf[tid - off] : 0u;
        __syncthreads();
        scanbuf[tid] += v;
        __syncthreads();
    }
    unsigned incl = scanbuf[tid];
    unsigned before = incl - part;
    if (before < Kneed && incl >= Kneed) {
        unsigned cum = before;
#pragma unroll
        for (int j = 0; j < 8; j++) {
            unsigned c = local[j];
            if (cum + c >= Kneed) {
                *s_bin = (SBINS - 1) - (tid * 8 + j);
                *s_above = cum;
                break;
            }
            cum += c;
        }
    }
    __syncthreads();
}

// Same for a 256-bin histogram.
__device__ void select_bin256(const unsigned* hist, unsigned* scanbuf, unsigned Kneed,
                              int tid, int* s_bin, unsigned* s_above) {
    unsigned cnt = 0;
    if (tid < 256) {
        cnt = hist[255 - tid];
        scanbuf[tid] = cnt;
    }
    __syncthreads();
    for (int off = 1; off < 256; off <<= 1) {
        unsigned v = (tid >= off && tid < 256) ? scanbuf[tid - off] : 0u;
        __syncthreads();
        if (tid < 256) scanbuf[tid] += v;
        __syncthreads();
    }
    if (tid < 256) {
        unsigned incl = scanbuf[tid];
        unsigned before = incl - cnt;
        if (before < Kneed && incl >= Kneed) {
            *s_bin = 255 - tid;
            *s_above = before;
        }
    }
    __syncthreads();
}

__global__ void __launch_bounds__(THREADS, 3)
vocab_project_kernel(const float* __restrict__ logits,
                     const void* __restrict__ mapping,
                     float* __restrict__ out) {
    __shared__ unsigned pool[256 + 2 * MAXB];     // phase1: 4096-bin hist; phase2: h256 + ping-pong
    __shared__ unsigned candKey[MAXB], candIdx[MAXB];
    __shared__ unsigned scanbuf[THREADS];
    __shared__ unsigned selKey[KSEL], selIdx[KSEL];
    __shared__ float    selW[KSEL];
    __shared__ int      selSid[KSEL];
    __shared__ int      s_bin;
    __shared__ unsigned s_above;
    __shared__ int      nCand, selCount, nNext, s_is64;
    __shared__ unsigned s_maxkey;

    const int tid = threadIdx.x;
    const int row = blockIdx.x;
    const float4* __restrict__ rp = (const float4*)(logits + (size_t)row * VT);
    float* __restrict__ orow = out + (size_t)row * VS;

    // ---- init + mapping dtype detect ----
    unsigned* hist = pool;
    for (int i = tid; i < SBINS; i += THREADS) hist[i] = 0u;
    if (tid == 0) {
        const unsigned* m32 = (const unsigned*)mapping;
        int all0 = 1;
        for (int i = 1; i < 64; i += 2)
            if (m32[i] != 0u) { all0 = 0; break; }
        s_is64 = all0;
        s_maxkey = 0u;
        selCount = 0;
    }
    __syncthreads();

    // ---- sample pass: every 16th float4 (8000 elems) -> 4096-bin hist ----
    for (int i = tid; i < VT / 64; i += THREADS) {
        float4 v = rp[i << 4];
        atomicAdd(&hist[f2k(v.x) >> 20], 1u);
        atomicAdd(&hist[f2k(v.y) >> 20], 1u);
        atomicAdd(&hist[f2k(v.z) >> 20], 1u);
        atomicAdd(&hist[f2k(v.w) >> 20], 1u);
    }
    __syncthreads();

    // threshold: sample rank 64 (~true rank 1000-1400, inside [KSEL, MAXB])
    select_bin4096(hist, scanbuf, 64u, tid, &s_bin, &s_above);
    int thr_bin = s_bin;

    // ---- full pass: collect (key, idx) >= threshold ----
    // Hot path: pure float compares (f2k is monotone => float order == key order).
    for (int attempt = 0; attempt < 6; attempt++) {
        if (tid == 0) nCand = 0;
        __syncthreads();
        const float thrVal = k2f((unsigned)thr_bin << 20);
        // 16 floats (4 x float4) per iteration; VT/16 = 8000 chunks
        for (int i = tid; i < VT / 16; i += THREADS) {
            const float4 a = rp[4 * i + 0];
            const float4 b = rp[4 * i + 1];
            const float4 c = rp[4 * i + 2];
            const float4 d = rp[4 * i + 3];
            float m0 = fmaxf(fmaxf(a.x, a.y), fmaxf(a.z, a.w));
            float m1 = fmaxf(fmaxf(b.x, b.y), fmaxf(b.z, b.w));
            float m2 = fmaxf(fmaxf(c.x, c.y), fmaxf(c.z, c.w));
            float m3 = fmaxf(fmaxf(d.x, d.y), fmaxf(d.z, d.w));
            if (fmaxf(fmaxf(m0, m1), fmaxf(m2, m3)) >= thrVal) {
                const float v[16] = {a.x,a.y,a.z,a.w, b.x,b.y,b.z,b.w,
                                     c.x,c.y,c.z,c.w, d.x,d.y,d.z,d.w};
#pragma unroll
                for (int j = 0; j < 16; j++) {
                    if (v[j] >= thrVal) {
                        int p = atomicAdd(&nCand, 1);
                        if (p < MAXB) {
                            candKey[p] = f2k(v[j]);
                            candIdx[p] = (unsigned)(i * 16 + j);
                        }
                    }
                }
            }
        }
        __syncthreads();
        int nc = nCand;
        if (nc >= KSEL && nc <= MAXB) break;
        if (nc < KSEL) thr_bin = (thr_bin >= 64) ? thr_bin - 64 : 0;
        else           thr_bin = thr_bin + 1;
        __syncthreads();
    }

    // ---- zero own output row ----
    {
        float4 z = make_float4(0.f, 0.f, 0.f, 0.f);
        float4* op = (float4*)orow;
        for (int i = tid; i < VS / 4; i += THREADS) op[i] = z;
    }

    // ---- exact top-KSEL among candidates: byte-radix select (msb->lsb) ----
    unsigned* h256   = pool;
    unsigned* tmpKey = pool + 256;
    unsigned* tmpIdx = pool + 256 + MAXB;
    unsigned *curK = candKey, *curI = candIdx, *othK = tmpKey, *othI = tmpIdx;
    int curN = nCand < MAXB ? nCand : MAXB;
    int need = KSEL;
    __syncthreads();

    for (int level = 3; level >= 0; level--) {
        if (curN == need) {
            for (int p = tid; p < curN; p += THREADS) {
                int q = atomicAdd(&selCount, 1);
                selKey[q] = curK[p]; selIdx[q] = curI[p];
            }
            need = 0;
            __syncthreads();
            break;
        }
        if (tid < 256) h256[tid] = 0u;
        __syncthreads();
        const int sh = level * 8;
        for (int p = tid; p < curN; p += THREADS)
            atomicAdd(&h256[(curK[p] >> sh) & 0xFFu], 1u);
        __syncthreads();
        select_bin256(h256, scanbuf, (unsigned)need, tid, &s_bin, &s_above);
        const int c = s_bin;
        const int G = (int)s_above;
        if (tid == 0) nNext = 0;
        __syncthreads();
        for (int p = tid; p < curN; p += THREADS) {
            unsigned key = curK[p];
            int byte = (int)((key >> sh) & 0xFFu);
            if (byte > c) {
                int q = atomicAdd(&selCount, 1);
                selKey[q] = key; selIdx[q] = curI[p];
            } else if (byte == c) {
                int q = atomicAdd(&nNext, 1);
                othK[q] = key; othI[q] = curI[p];
            }
        }
        __syncthreads();
        need -= G;
        curN = nNext;
        unsigned* t;
        t = curK; curK = othK; othK = t;
        t = curI; curI = othI; othI = t;
        __syncthreads();
    }

    // remaining curN entries have IDENTICAL keys; take `need` smallest indices
    if (need > 0) {
        for (int p = tid; p < curN; p += THREADS) {
            unsigned my = curI[p];
            int rank = 0;
            for (int j = 0; j < curN; j++) rank += (curI[j] < my);
            if (rank < need) {
                int q = atomicAdd(&selCount, 1);
                selKey[q] = curK[p]; selIdx[q] = my;
            }
        }
        __syncthreads();
    }

    // ---- canonicalize: bitonic sort KSEL winners by index ascending ----
    for (int k = 2; k <= KSEL; k <<= 1) {
        for (int j = k >> 1; j > 0; j >>= 1) {
            if (tid < KSEL) {
                int ixj = tid ^ j;
                if (ixj > tid) {
                    bool up = ((tid & k) == 0);
                    unsigned a = selIdx[tid], b = selIdx[ixj];
                    if ((a > b) == up) {
                        selIdx[tid] = b; selIdx[ixj] = a;
                        unsigned t = selKey[tid]; selKey[tid] = selKey[ixj]; selKey[ixj] = t;
                    }
                }
            }
            __syncthreads();
        }
    }

    // ---- max logit over selection ----
    if (tid < KSEL) atomicMax(&s_maxkey, selKey[tid]);
    __syncthreads();
    const float vmax = k2f(s_maxkey);

    // ---- weights + deterministic fixed-order denominator ----
    float* red = (float*)scanbuf;
    if (tid < KSEL) {
        float w = exp2f((k2f(selKey[tid]) - vmax) * 0.36067376022224085f); // 1/(4 ln2)
        selW[tid] = w;
        red[tid] = w;
    }
    __syncthreads();
    for (int s = KSEL / 2; s > 0; s >>= 1) {
        if (tid < s) red[tid] += red[tid + s];
        __syncthreads();
    }
    const float inv = 1.0f / red[0];

    // ---- gather student ids ----
    if (tid < KSEL) {
        unsigned idx = selIdx[tid];
        int sid;
        if (s_is64) sid = (int)((const long long*)mapping)[idx];
        else        sid = ((const int*)mapping)[idx];
        selSid[tid] = sid;
    }
    __syncthreads();

    // ---- dedup'd deterministic scatter (idx-sorted => fixed sum order) ----
    if (tid < KSEL) {
        int sid = selSid[tid];
        bool first = true;
        for (int j = 0; j < tid; j++)
            if (selSid[j] == sid) { first = false; break; }
        if (first) {
            float s = 0.f;
            for (int j = tid; j < KSEL; j++)
                if (selSid[j] == sid) s += selW[j];
            orow[sid] = s * inv;
        }
    }
}

extern "C" void kernel_launch(void* const* d_in, const int* in_sizes, int n_in,
                              void* d_out, int out_size) {
    const float* logits  = (const float*)d_in[0];
    const void*  mapping = d_in[1];
    float* out = (float*)d_out;
    int rows = in_sizes[0] / VT;   // B*T = 2048
    vocab_project_kernel<<<rows, THREADS>>>(logits, mapping, out);
}

// round 4
// speedup vs baseline: 1.3509x; 1.3063x over previous
#include <cuda_runtime.h>
#include <cuda_bf16.h>

#define THREADS 512
#define VT      128000
#define VS      32000
#define KSEL    256
#define MAXB    2048

// monotone float->uint key
__device__ __forceinline__ unsigned f2k(float x) {
    unsigned u = __float_as_uint(x);
    return (u & 0x80000000u) ? ~u : (u | 0x80000000u);
}
__device__ __forceinline__ float k2f(unsigned k) {
    unsigned u = (k & 0x80000000u) ? (k & 0x7fffffffu) : ~k;
    return __uint_as_float(u);
}

// 256-bin hist: find bin (from top) where cumulative crosses Kneed.
__device__ void select_bin256(const unsigned* hist, unsigned* scanbuf, unsigned Kneed,
                              int tid, int* s_bin, unsigned* s_above) {
    unsigned cnt = 0;
    if (tid < 256) {
        cnt = hist[255 - tid];
        scanbuf[tid] = cnt;
    }
    __syncthreads();
    for (int off = 1; off < 256; off <<= 1) {
        unsigned v = (tid >= off && tid < 256) ? scanbuf[tid - off] : 0u;
        __syncthreads();
        if (tid < 256) scanbuf[tid] += v;
        __syncthreads();
    }
    if (tid < 256) {
        unsigned incl = scanbuf[tid];
        unsigned before = incl - cnt;
        if (before < Kneed && incl >= Kneed) {
            *s_bin = 255 - tid;
            *s_above = before;
        }
    }
    __syncthreads();
}

__global__ void __launch_bounds__(THREADS, 4)
vocab_project_kernel(const float* __restrict__ logits,
                     const void* __restrict__ mapping,
                     float* __restrict__ out) {
    __shared__ unsigned pool[256 + 2 * MAXB];     // h256 + radix ping-pong
    __shared__ unsigned candKey[MAXB], candIdx[MAXB];
    __shared__ unsigned scanbuf[THREADS];
    __shared__ float    fred[THREADS];            // stats reduction
    __shared__ unsigned selKey[KSEL], selIdx[KSEL];
    __shared__ float    selW[KSEL];
    __shared__ int      selSid[KSEL];
    __shared__ int      s_bin;
    __shared__ unsigned s_above;
    __shared__ int      nCand, selCount, nNext, s_is64;
    __shared__ unsigned s_maxkey;
    __shared__ float    s_mean, s_std;

    const int tid = threadIdx.x;
    const int row = blockIdx.x;
    const float* __restrict__ rowf = logits + (size_t)row * VT;
    const float4* __restrict__ rp = (const float4*)rowf;
    float* __restrict__ orow = out + (size_t)row * VS;

    // ---- init + mapping dtype detect ----
    if (tid == 0) {
        const unsigned* m32 = (const unsigned*)mapping;
        int all0 = 1;
        for (int i = 1; i < 64; i += 2)
            if (m32[i] != 0u) { all0 = 0; break; }
        s_is64 = all0;
        s_maxkey = 0u;
        selCount = 0;
    }

    // ---- cheap stats: 512 strided samples -> mean/std -> threshold ----
    {
        float x = rowf[tid * (VT / THREADS)];   // stride 250
        fred[tid] = x;
        ((float*)scanbuf)[tid] = x * x;
        __syncthreads();
        for (int s = THREADS / 2; s > 0; s >>= 1) {
            if (tid < s) {
                fred[tid] += fred[tid + s];
                ((float*)scanbuf)[tid] += ((float*)scanbuf)[tid + s];
            }
            __syncthreads();
        }
        if (tid == 0) {
            float mean = fred[0] * (1.0f / THREADS);
            float var  = ((float*)scanbuf)[0] * (1.0f / THREADS) - mean * mean;
            s_mean = mean;
            s_std  = sqrtf(fmaxf(var, 1e-12f));
        }
        __syncthreads();
    }

    // ---- full pass: collect (key, idx) >= threshold ----
    float thrVal = s_mean + 2.45f * s_std;   // E[count] ~ 900 for gaussian rows
    for (int attempt = 0; attempt < 8; attempt++) {
        if (tid == 0) nCand = 0;
        __syncthreads();
        for (int i = tid; i < VT / 16; i += THREADS) {
            const float4 a = rp[4 * i + 0];
            const float4 b = rp[4 * i + 1];
            const float4 c = rp[4 * i + 2];
            const float4 d = rp[4 * i + 3];
            float m0 = fmaxf(fmaxf(a.x, a.y), fmaxf(a.z, a.w));
            float m1 = fmaxf(fmaxf(b.x, b.y), fmaxf(b.z, b.w));
            float m2 = fmaxf(fmaxf(c.x, c.y), fmaxf(c.z, c.w));
            float m3 = fmaxf(fmaxf(d.x, d.y), fmaxf(d.z, d.w));
            if (fmaxf(fmaxf(m0, m1), fmaxf(m2, m3)) >= thrVal) {
                const float v[16] = {a.x,a.y,a.z,a.w, b.x,b.y,b.z,b.w,
                                     c.x,c.y,c.z,c.w, d.x,d.y,d.z,d.w};
#pragma unroll
                for (int j = 0; j < 16; j++) {
                    if (v[j] >= thrVal) {
                        int p = atomicAdd(&nCand, 1);
                        if (p < MAXB) {
                            candKey[p] = f2k(v[j]);
                            candIdx[p] = (unsigned)(i * 16 + j);
                        }
                    }
                }
            }
        }
        __syncthreads();
        int nc = nCand;
        if (nc >= KSEL && nc <= MAXB) break;
        // practically never taken on this data; guarantees correctness otherwise
        if (nc < KSEL) thrVal -= 0.60f * s_std + 1e-6f;
        else           thrVal += 0.35f * s_std + 1e-6f;
        __syncthreads();
    }

    // ---- zero own output row (overlaps selection tail below) ----
    {
        float4 z = make_float4(0.f, 0.f, 0.f, 0.f);
        float4* op = (float4*)orow;
        for (int i = tid; i < VS / 4; i += THREADS) op[i] = z;
    }

    // ---- exact top-KSEL among candidates: byte-radix select (msb->lsb) ----
    unsigned* h256   = pool;
    unsigned* tmpKey = pool + 256;
    unsigned* tmpIdx = pool + 256 + MAXB;
    unsigned *curK = candKey, *curI = candIdx, *othK = tmpKey, *othI = tmpIdx;
    int curN = nCand < MAXB ? nCand : MAXB;
    int need = KSEL;
    __syncthreads();

    for (int level = 3; level >= 0; level--) {
        if (curN == need) {
            for (int p = tid; p < curN; p += THREADS) {
                int q = atomicAdd(&selCount, 1);
                selKey[q] = curK[p]; selIdx[q] = curI[p];
            }
            need = 0;
            __syncthreads();
            break;
        }
        if (tid < 256) h256[tid] = 0u;
        __syncthreads();
        const int sh = level * 8;
        for (int p = tid; p < curN; p += THREADS)
            atomicAdd(&h256[(curK[p] >> sh) & 0xFFu], 1u);
        __syncthreads();
        select_bin256(h256, scanbuf, (unsigned)need, tid, &s_bin, &s_above);
        const int c = s_bin;
        const int G = (int)s_above;
        if (tid == 0) nNext = 0;
        __syncthreads();
        for (int p = tid; p < curN; p += THREADS) {
            unsigned key = curK[p];
            int byte = (int)((key >> sh) & 0xFFu);
            if (byte > c) {
                int q = atomicAdd(&selCount, 1);
                selKey[q] = key; selIdx[q] = curI[p];
            } else if (byte == c) {
                int q = atomicAdd(&nNext, 1);
                othK[q] = key; othI[q] = curI[p];
            }
        }
        __syncthreads();
        need -= G;
        curN = nNext;
        unsigned* t;
        t = curK; curK = othK; othK = t;
        t = curI; curI = othI; othI = t;
        __syncthreads();
    }

    // remaining curN entries have IDENTICAL keys; take `need` smallest indices
    if (need > 0) {
        for (int p = tid; p < curN; p += THREADS) {
            unsigned my = curI[p];
            int rank = 0;
            for (int j = 0; j < curN; j++) rank += (curI[j] < my);
            if (rank < need) {
                int q = atomicAdd(&selCount, 1);
                selKey[q] = curK[p]; selIdx[q] = my;
            }
        }
        __syncthreads();
    }

    // ---- canonicalize: bitonic sort KSEL winners by index ascending ----
    for (int k = 2; k <= KSEL; k <<= 1) {
        for (int j = k >> 1; j > 0; j >>= 1) {
            if (tid < KSEL) {
                int ixj = tid ^ j;
                if (ixj > tid) {
                    bool up = ((tid & k) == 0);
                    unsigned a = selIdx[tid], b = selIdx[ixj];
                    if ((a > b) == up) {
                        selIdx[tid] = b; selIdx[ixj] = a;
                        unsigned t = selKey[tid]; selKey[tid] = selKey[ixj]; selKey[ixj] = t;
                    }
                }
            }
            __syncthreads();
        }
    }

    // ---- max logit over selection ----
    if (tid < KSEL) atomicMax(&s_maxkey, selKey[tid]);
    __syncthreads();
    const float vmax = k2f(s_maxkey);

    // ---- weights + deterministic fixed-order denominator ----
    float* red = (float*)scanbuf;
    if (tid < KSEL) {
        float w = exp2f((k2f(selKey[tid]) - vmax) * 0.36067376022224085f); // 1/(4 ln2)
        selW[tid] = w;
        red[tid] = w;
    }
    __syncthreads();
    for (int s = KSEL / 2; s > 0; s >>= 1) {
        if (tid < s) red[tid] += red[tid + s];
        __syncthreads();
    }
    const float inv = 1.0f / red[0];

    // ---- gather student ids ----
    if (tid < KSEL) {
        unsigned idx = selIdx[tid];
        int sid;
        if (s_is64) sid = (int)((const long long*)mapping)[idx];
        else        sid = ((const int*)mapping)[idx];
        selSid[tid] = sid;
    }
    __syncthreads();

    // ---- dedup'd deterministic scatter (idx-sorted => fixed sum order) ----
    if (tid < KSEL) {
        int sid = selSid[tid];
        bool first = true;
        for (int j = 0; j < tid; j++)
            if (selSid[j] == sid) { first = false; break; }
        if (first) {
            float s = 0.f;
            for (int j = tid; j < KSEL; j++)
                if (selSid[j] == sid) s += selW[j];
            orow[sid] = s * inv;
        }
    }
}

extern "C" void kernel_launch(void* const* d_in, const int* in_sizes, int n_in,
                              void* d_out, int out_size) {
    const float* logits  = (const float*)d_in[0];
    const void*  mapping = d_in[1];
    float* out = (float*)d_out;
    int rows = in_sizes[0] / VT;   // B*T = 2048
    vocab_project_kernel<<<rows, THREADS>>>(logits, mapping, out);
}

// round 5
// speedup vs baseline: 1.6722x; 1.2378x over previous
#include <cuda_runtime.h>
#include <cuda_bf16.h>

#define THREADS 512
#define VT      128000
#define VS      32000
#define KSEL    256
#define MAXB    2048

// monotone float->uint key
__device__ __forceinline__ unsigned f2k(float x) {
    unsigned u = __float_as_uint(x);
    return (u & 0x80000000u) ? ~u : (u | 0x80000000u);
}
__device__ __forceinline__ float k2f(unsigned k) {
    unsigned u = (k & 0x80000000u) ? (k & 0x7fffffffu) : ~k;
    return __uint_as_float(u);
}

__global__ void __launch_bounds__(THREADS, 4)
vocab_project_kernel(const float* __restrict__ logits,
                     const void* __restrict__ mapping,
                     float* __restrict__ out) {
    __shared__ unsigned h256[256];
    __shared__ unsigned tKey[2][MAXB], tIdx[2][MAXB];
    __shared__ float    fred[THREADS];
    __shared__ float    fred2[THREADS];
    __shared__ unsigned selKey[KSEL], selIdx[KSEL];
    __shared__ int      s_bin;
    __shared__ unsigned s_above;
    __shared__ int      nCand, selCount, nNext, s_is64;
    __shared__ unsigned s_maxkey;
    __shared__ float    s_mean, s_std, s_denom;

    const int tid = threadIdx.x;
    const int row = blockIdx.x;
    const float* __restrict__ rowf = logits + (size_t)row * VT;
    const float4* __restrict__ rp = (const float4*)rowf;
    float* __restrict__ orow = out + (size_t)row * VS;

    // ---- init + mapping dtype detect ----
    if (tid == 0) {
        const unsigned* m32 = (const unsigned*)mapping;
        int all0 = 1;
        for (int i = 1; i < 64; i += 2)
            if (m32[i] != 0u) { all0 = 0; break; }
        s_is64 = all0;
        s_maxkey = 0u;
        s_denom = 0.0f;
        selCount = 0;
    }

    // ---- cheap stats: 512 strided samples -> mean/std -> threshold ----
    {
        float x = rowf[tid * (VT / THREADS)];
        fred[tid] = x;
        fred2[tid] = x * x;
        __syncthreads();
        for (int s = THREADS / 2; s > 0; s >>= 1) {
            if (tid < s) {
                fred[tid] += fred[tid + s];
                fred2[tid] += fred2[tid + s];
            }
            __syncthreads();
        }
        if (tid == 0) {
            float mean = fred[0] * (1.0f / THREADS);
            float var  = fred2[0] * (1.0f / THREADS) - mean * mean;
            s_mean = mean;
            s_std  = sqrtf(fmaxf(var, 1e-12f));
        }
        __syncthreads();
    }

    // ---- full pass: collect (key, idx) >= threshold ----
    float thrVal = s_mean + 2.45f * s_std;   // E[count] ~ 900
    for (int attempt = 0; attempt < 8; attempt++) {
        if (tid == 0) nCand = 0;
        __syncthreads();
        for (int i = tid; i < VT / 16; i += THREADS) {
            const float4 a = rp[4 * i + 0];
            const float4 b = rp[4 * i + 1];
            const float4 c = rp[4 * i + 2];
            const float4 d = rp[4 * i + 3];
            float m0 = fmaxf(fmaxf(a.x, a.y), fmaxf(a.z, a.w));
            float m1 = fmaxf(fmaxf(b.x, b.y), fmaxf(b.z, b.w));
            float m2 = fmaxf(fmaxf(c.x, c.y), fmaxf(c.z, c.w));
            float m3 = fmaxf(fmaxf(d.x, d.y), fmaxf(d.z, d.w));
            if (fmaxf(fmaxf(m0, m1), fmaxf(m2, m3)) >= thrVal) {
                const float v[16] = {a.x,a.y,a.z,a.w, b.x,b.y,b.z,b.w,
                                     c.x,c.y,c.z,c.w, d.x,d.y,d.z,d.w};
#pragma unroll
                for (int j = 0; j < 16; j++) {
                    if (v[j] >= thrVal) {
                        int p = atomicAdd(&nCand, 1);
                        if (p < MAXB) {
                            tKey[0][p] = f2k(v[j]);
                            tIdx[0][p] = (unsigned)(i * 16 + j);
                        }
                    }
                }
            }
        }
        __syncthreads();
        int nc = nCand;
        if (nc >= KSEL && nc <= MAXB) break;
        if (nc < KSEL) thrVal -= 0.60f * s_std + 1e-6f;
        else           thrVal += 0.35f * s_std + 1e-6f;
        __syncthreads();
    }

    // ---- zero own output row ----
    {
        float4 z = make_float4(0.f, 0.f, 0.f, 0.f);
        float4* op = (float4*)orow;
        for (int i = tid; i < VS / 4; i += THREADS) op[i] = z;
    }

    // ---- exact top-KSEL: byte-radix select (msb->lsb), ping-pong tiers ----
    int cur = 0;
    int curN = nCand < MAXB ? nCand : MAXB;
    int need = KSEL;
    __syncthreads();

    for (int level = 3; level >= 0 && need > 0; level--) {
        if (curN == need) {
            for (int p = tid; p < curN; p += THREADS) {
                int q = atomicAdd(&selCount, 1);
                selKey[q] = tKey[cur][p]; selIdx[q] = tIdx[cur][p];
            }
            need = 0;
            __syncthreads();
            break;
        }
        if (tid < 256) h256[tid] = 0u;
        __syncthreads();
        const int sh = level * 8;
        for (int p = tid; p < curN; p += THREADS)
            atomicAdd(&h256[(tKey[cur][p] >> sh) & 0xFFu], 1u);
        __syncthreads();
        // single-warp top-down scan over 256 bins: find crossing bin
        if (tid < 32) {
            unsigned local[8];
            unsigned part = 0;
#pragma unroll
            for (int j = 0; j < 8; j++) {
                local[j] = h256[255 - (tid * 8 + j)];
                part += local[j];
            }
            unsigned incl = part;
#pragma unroll
            for (int off = 1; off < 32; off <<= 1) {
                unsigned v = __shfl_up_sync(0xffffffffu, incl, off);
                if (tid >= off) incl += v;
            }
            unsigned before = incl - part;
            if (before < (unsigned)need && incl >= (unsigned)need) {
                unsigned cum = before;
#pragma unroll
                for (int j = 0; j < 8; j++) {
                    unsigned c = local[j];
                    if (cum + c >= (unsigned)need) {
                        s_bin = 255 - (tid * 8 + j);
                        s_above = cum;
                        break;
                    }
                    cum += c;
                }
            }
        }
        if (tid == 0) nNext = 0;
        __syncthreads();
        const int c = s_bin;
        const int G = (int)s_above;
        const int oth = cur ^ 1;
        for (int p = tid; p < curN; p += THREADS) {
            unsigned key = tKey[cur][p];
            int byte = (int)((key >> sh) & 0xFFu);
            if (byte > c) {
                int q = atomicAdd(&selCount, 1);
                selKey[q] = key; selIdx[q] = tIdx[cur][p];
            } else if (byte == c) {
                int q = atomicAdd(&nNext, 1);
                tKey[oth][q] = key; tIdx[oth][q] = tIdx[cur][p];
            }
        }
        __syncthreads();
        need -= G;
        curN = nNext;
        cur = oth;
        __syncthreads();
    }

    // remaining entries have IDENTICAL keys; take `need` smallest indices
    if (need > 0) {
        for (int p = tid; p < curN; p += THREADS) {
            unsigned my = tIdx[cur][p];
            int rank = 0;
            for (int j = 0; j < curN; j++) rank += (tIdx[cur][j] < my);
            if (rank < need) {
                int q = atomicAdd(&selCount, 1);
                selKey[q] = tKey[cur][p]; selIdx[q] = my;
            }
        }
        __syncthreads();
    }

    // ---- max logit over selection ----
    if (tid < KSEL) atomicMax(&s_maxkey, selKey[tid]);
    __syncthreads();
    const float vmax = k2f(s_maxkey);

    // ---- weights + denominator (warp shfl reduce + shared atomics) ----
    float w = 0.0f;
    if (tid < KSEL)
        w = exp2f((k2f(selKey[tid]) - vmax) * 0.36067376022224085f); // 1/(4 ln2)
    if (tid < KSEL) {
        float ws = w;
#pragma unroll
        for (int off = 16; off > 0; off >>= 1)
            ws += __shfl_xor_sync(0xffffffffu, ws, off);
        if ((tid & 31) == 0) atomicAdd(&s_denom, ws);
    }
    __syncthreads();
    const float inv = 1.0f / s_denom;

    // ---- scatter: gather sid, atomic add into zeroed row (handles dups) ----
    if (tid < KSEL) {
        unsigned idx = selIdx[tid];
        int sid;
        if (s_is64) sid = (int)((const long long*)mapping)[idx];
        else        sid = ((const int*)mapping)[idx];
        atomicAdd(&orow[sid], w * inv);
    }
}

extern "C" void kernel_launch(void* const* d_in, const int* in_sizes, int n_in,
                              void* d_out, int out_size) {
    const float* logits  = (const float*)d_in[0];
    const void*  mapping = d_in[1];
    float* out = (float*)d_out;
    int rows = in_sizes[0] / VT;   // B*T = 2048
    vocab_project_kernel<<<rows, THREADS>>>(logits, mapping, out);
}

// round 6
// speedup vs baseline: 1.9128x; 1.1439x over previous
#include <cuda_runtime.h>
#include <cuda_bf16.h>

#define THREADS 512
#define VT      128000
#define VS      32000
#define KSEL    256
#define MAXB    2048

// monotone float->uint key
__device__ __forceinline__ unsigned f2k(float x) {
    unsigned u = __float_as_uint(x);
    return (u & 0x80000000u) ? ~u : (u | 0x80000000u);
}
__device__ __forceinline__ float k2f(unsigned k) {
    unsigned u = (k & 0x80000000u) ? (k & 0x7fffffffu) : ~k;
    return __uint_as_float(u);
}

__global__ void __launch_bounds__(THREADS, 4)
vocab_project_kernel(const float* __restrict__ logits,
                     const void* __restrict__ mapping,
                     float* __restrict__ out) {
    __shared__ unsigned h256[256];
    __shared__ unsigned tKey[2][MAXB], tIdx[2][MAXB];
    __shared__ float    fred[THREADS];
    __shared__ float    fred2[THREADS];
    __shared__ unsigned selKey[KSEL], selIdx[KSEL];
    __shared__ int      s_bin;
    __shared__ unsigned s_above;
    __shared__ int      nCand, selCount, nNext, s_is64;
    __shared__ unsigned s_maxkey, s_minkey;
    __shared__ float    s_mean, s_std, s_denom;

    const int tid = threadIdx.x;
    const int row = blockIdx.x;
    const float* __restrict__ rowf = logits + (size_t)row * VT;
    const float4* __restrict__ rp = (const float4*)rowf;
    float* __restrict__ orow = out + (size_t)row * VS;

    // ---- init + mapping dtype detect ----
    if (tid == 0) {
        const unsigned* m32 = (const unsigned*)mapping;
        int all0 = 1;
        for (int i = 1; i < 64; i += 2)
            if (m32[i] != 0u) { all0 = 0; break; }
        s_is64 = all0;
        s_denom = 0.0f;
        selCount = 0;
    }

    // ---- full pass: collect (key, idx) >= threshold ----
    // Common case: fixed threshold tuned for ~N(0,1) rows. If the count lands
    // outside [KSEL, MAXB], compute sampled stats once and retry (any input).
    float thrVal = 2.45f;               // E[count] ~ 915 for standard normal
    float stdGuess = 1.0f;
    bool haveStats = false;
    for (int attempt = 0; attempt < 10; attempt++) {
        if (tid == 0) { nCand = 0; s_maxkey = 0u; s_minkey = 0xFFFFFFFFu; }
        __syncthreads();
        for (int i = tid; i < VT / 16; i += THREADS) {
            const float4 a = rp[4 * i + 0];
            const float4 b = rp[4 * i + 1];
            const float4 c = rp[4 * i + 2];
            const float4 d = rp[4 * i + 3];
            float m0 = fmaxf(fmaxf(a.x, a.y), fmaxf(a.z, a.w));
            float m1 = fmaxf(fmaxf(b.x, b.y), fmaxf(b.z, b.w));
            float m2 = fmaxf(fmaxf(c.x, c.y), fmaxf(c.z, c.w));
            float m3 = fmaxf(fmaxf(d.x, d.y), fmaxf(d.z, d.w));
            if (fmaxf(fmaxf(m0, m1), fmaxf(m2, m3)) >= thrVal) {
                const float v[16] = {a.x,a.y,a.z,a.w, b.x,b.y,b.z,b.w,
                                     c.x,c.y,c.z,c.w, d.x,d.y,d.z,d.w};
#pragma unroll
                for (int j = 0; j < 16; j++) {
                    if (v[j] >= thrVal) {
                        unsigned key = f2k(v[j]);
                        int p = atomicAdd(&nCand, 1);
                        if (p < MAXB) {
                            tKey[0][p] = key;
                            tIdx[0][p] = (unsigned)(i * 16 + j);
                            atomicMax(&s_maxkey, key);
                            atomicMin(&s_minkey, key);
                        }
                    }
                }
            }
        }
        __syncthreads();
        int nc = nCand;
        if (nc >= KSEL && nc <= MAXB) break;
        if (!haveStats) {
            // sampled mean/std (rare path)
            float x = rowf[tid * (VT / THREADS)];
            fred[tid] = x;
            fred2[tid] = x * x;
            __syncthreads();
            for (int s = THREADS / 2; s > 0; s >>= 1) {
                if (tid < s) {
                    fred[tid] += fred[tid + s];
                    fred2[tid] += fred2[tid + s];
                }
                __syncthreads();
            }
            if (tid == 0) {
                float mean = fred[0] * (1.0f / THREADS);
                float var  = fred2[0] * (1.0f / THREADS) - mean * mean;
                s_mean = mean;
                s_std  = sqrtf(fmaxf(var, 1e-12f));
            }
            __syncthreads();
            stdGuess = s_std;
            float cand = s_mean + 2.45f * s_std;
            // if stats give (nearly) the same threshold that just failed, nudge it
            if (fabsf(cand - thrVal) < 0.05f * s_std)
                cand += (nc < KSEL) ? -0.60f * s_std : 0.35f * s_std;
            thrVal = cand;
            haveStats = true;
        } else {
            if (nc < KSEL) thrVal -= 0.60f * stdGuess + 1e-6f;
            else           thrVal += 0.35f * stdGuess + 1e-6f;
        }
        __syncthreads();
    }

    // ---- zero own output row (stores pipeline behind selection) ----
    {
        float4 z = make_float4(0.f, 0.f, 0.f, 0.f);
        float4* op = (float4*)orow;
        for (int i = tid; i < VS / 4; i += THREADS) op[i] = z;
    }

    // ---- exact top-KSEL: byte-radix select starting at highest differing byte ----
    int cur = 0;
    int curN = nCand < MAXB ? nCand : MAXB;
    int need = KSEL;
    const unsigned keyxor = s_minkey ^ s_maxkey;
    int level_start = (keyxor == 0u) ? -1 : (3 - (__clz(keyxor) >> 3));
    __syncthreads();

    for (int level = level_start; level >= 0 && need > 0; level--) {
        if (curN == need) {
            for (int p = tid; p < curN; p += THREADS) {
                int q = atomicAdd(&selCount, 1);
                selKey[q] = tKey[cur][p]; selIdx[q] = tIdx[cur][p];
            }
            need = 0;
            __syncthreads();
            break;
        }
        if (tid < 256) h256[tid] = 0u;
        __syncthreads();
        const int sh = level * 8;
        for (int p = tid; p < curN; p += THREADS)
            atomicAdd(&h256[(tKey[cur][p] >> sh) & 0xFFu], 1u);
        __syncthreads();
        // single-warp top-down scan over 256 bins: find crossing bin
        if (tid < 32) {
            unsigned local[8];
            unsigned part = 0;
#pragma unroll
            for (int j = 0; j < 8; j++) {
                local[j] = h256[255 - (tid * 8 + j)];
                part += local[j];
            }
            unsigned incl = part;
#pragma unroll
            for (int off = 1; off < 32; off <<= 1) {
                unsigned v = __shfl_up_sync(0xffffffffu, incl, off);
                if (tid >= off) incl += v;
            }
            unsigned before = incl - part;
            if (before < (unsigned)need && incl >= (unsigned)need) {
                unsigned cum = before;
#pragma unroll
                for (int j = 0; j < 8; j++) {
                    unsigned c = local[j];
                    if (cum + c >= (unsigned)need) {
                        s_bin = 255 - (tid * 8 + j);
                        s_above = cum;
                        break;
                    }
                    cum += c;
                }
            }
        }
        if (tid == 0) nNext = 0;
        __syncthreads();
        const int c = s_bin;
        const int G = (int)s_above;
        const int oth = cur ^ 1;
        for (int p = tid; p < curN; p += THREADS) {
            unsigned key = tKey[cur][p];
            int byte = (int)((key >> sh) & 0xFFu);
            if (byte > c) {
                int q = atomicAdd(&selCount, 1);
                selKey[q] = key; selIdx[q] = tIdx[cur][p];
            } else if (byte == c) {
                int q = atomicAdd(&nNext, 1);
                tKey[oth][q] = key; tIdx[oth][q] = tIdx[cur][p];
            }
        }
        __syncthreads();
        need -= G;
        curN = nNext;
        cur = oth;
        __syncthreads();
    }

    // remaining entries have IDENTICAL keys; take `need` smallest indices
    if (need > 0) {
        for (int p = tid; p < curN; p += THREADS) {
            unsigned my = tIdx[cur][p];
            int rank = 0;
            for (int j = 0; j < curN; j++) rank += (tIdx[cur][j] < my);
            if (rank < need) {
                int q = atomicAdd(&selCount, 1);
                selKey[q] = tKey[cur][p]; selIdx[q] = my;
            }
        }
        __syncthreads();
    }

    // ---- max logit = global max key (tracked during collection) ----
    const float vmax = k2f(s_maxkey);

    // ---- weights + denominator (warp shfl reduce + shared atomics) ----
    float w = 0.0f;
    if (tid < KSEL) {
        w = exp2f((k2f(selKey[tid]) - vmax) * 0.36067376022224085f); // 1/(4 ln2)
        float ws = w;
#pragma unroll
        for (int off = 16; off > 0; off >>= 1)
            ws += __shfl_xor_sync(0xffffffffu, ws, off);
        if ((tid & 31) == 0) atomicAdd(&s_denom, ws);
    }
    __syncthreads();
    const float inv = 1.0f / s_denom;

    // ---- scatter: gather sid, atomic add into zeroed row (handles dups) ----
    if (tid < KSEL) {
        unsigned idx = selIdx[tid];
        int sid;
        if (s_is64) sid = (int)((const long long*)mapping)[idx];
        else        sid = ((const int*)mapping)[idx];
        atomicAdd(&orow[sid], w * inv);
    }
}

extern "C" void kernel_launch(void* const* d_in, const int* in_sizes, int n_in,
                              void* d_out, int out_size) {
    const float* logits  = (const float*)d_in[0];
    const void*  mapping = d_in[1];
    float* out = (float*)d_out;
    int rows = in_sizes[0] / VT;   // B*T = 2048
    vocab_project_kernel<<<rows, THREADS>>>(logits, mapping, out);
}